// round 13
// baseline (speedup 1.0000x reference)
#include <cuda_runtime.h>
#include <cuda_fp16.h>
#include <cstdint>

#define NB   4
#define NT   4096
#define ND   2048
#define NBOT 256
#define NQK  512        // merged q|k output width

static constexpr int BM = 128, BN = 128, BK = 64, NTH = 128, NSTAGE = 3;
static constexpr int STAGE_B   = BM * 128 + BN * 128;  // A 16KB + B 16KB (fp16, 128B/row)
static constexpr int SMEM_BYTES = NSTAGE * STAGE_B;    // 96 KB per CTA (2 CTAs/SM = 192 KB)

// ---- scratch (__device__ globals: allocation-free rule) ----
__device__ __align__(256) float  g_S [(size_t)NB * NT * NT];    // fp32 scores (lower tri only)
__device__ __align__(256) __half g_C [(size_t)NB * NT * NT];    // fp16 combined matrix
__device__ __align__(256) __half g_Xh [(size_t)NB * NT * ND];   // X  fp16
__device__ __align__(256) __half g_Xth[(size_t)NB * ND * NT];   // X^T fp16
__device__ __align__(256) __half g_qk[(size_t)NB * NT * NQK];   // [q|k] fp16
__device__ __align__(256) __half g_W [(size_t)NQK * ND];        // [Wq;Wk] fp16
__device__ __align__(256) float  g_bias[NQK];

// ---- helpers ----
__device__ __forceinline__ uint32_t smem_u32(const void* p) {
    uint32_t a;
    asm("{ .reg .u64 t; cvta.to.shared.u64 t, %1; cvt.u32.u64 %0, t; }" : "=r"(a) : "l"(p));
    return a;
}
__device__ __forceinline__ void cp16(uint32_t dst, const __half* src) {
    asm volatile("cp.async.cg.shared.global [%0], [%1], 16;\n"
                 :: "r"(dst), "l"(__cvta_generic_to_global(src)));
}
#define CP_COMMIT()  asm volatile("cp.async.commit_group;\n" ::: "memory")
#define CP_WAIT(n)   asm volatile("cp.async.wait_group %0;\n" :: "n"(n) : "memory")

__device__ __forceinline__ void mma16(float* c, uint32_t a0, uint32_t a1, uint32_t a2,
                                      uint32_t a3, uint32_t b0, uint32_t b1) {
    asm volatile(
        "mma.sync.aligned.m16n8k16.row.col.f32.f16.f16.f32 "
        "{%0,%1,%2,%3}, {%4,%5,%6,%7}, {%8,%9}, {%0,%1,%2,%3};\n"
        : "+f"(c[0]), "+f"(c[1]), "+f"(c[2]), "+f"(c[3])
        : "r"(a0), "r"(a1), "r"(a2), "r"(a3), "r"(b0), "r"(b1));
}

// ============================================================================
// fp16 mma.sync GEMM: D[m][n] = sum_k A[m][k] * B[n][k]  (A,B fp16 row-major K-contig)
// EPI: 0 = fp32 store, 1 = +bias -> fp16 store, 2 = scale + causal(-4) mask -> fp32
//      (EPI 2: fully-masked tiles (n0 > m0) skipped; softmax reads only the prefix)
// CTA tile 128x128, 4 warps (2m x 2n), warp tile 64x64, BK=64 (128B smem rows),
// 3-stage cp.async ring (2 tiles in flight), __launch_bounds__(128,2) -> 2 CTAs/SM.
// Inner loop: per k-half, ALL 16 fragment LDS.128 are batched first, then the 64
// HMMA issue as one uninterrupted burst (widens LDS->mma dependency distance so
// the other warp's mma run overlaps this warp's load block).
// Smem chunk swizzle: chunk c of row r at c' = (c + 4*(r&1)) & 7 (conflict-free).
// Frag loads use a per-thread k-slot permutation identical for A and B.
// ============================================================================
template <int EPI>
__global__ void __launch_bounds__(NTH, 2)
gemm_h(const __half* __restrict__ A, int lda, long long strA,
       const __half* __restrict__ Bg, int ldb, long long strB,
       void* __restrict__ Cv, int ldc, long long strC,
       int K, const float* __restrict__ bias, float scale)
{
    const int m0 = blockIdx.y * BM;
    const int n0 = blockIdx.x * BN;
    const int bz = blockIdx.z;
    if (EPI == 2 && n0 > m0) return;   // fully masked tile: never written, never read

    const int tid = threadIdx.x, wid = tid >> 5, lane = tid & 31;
    const int g = lane >> 2, tg = lane & 3;

    extern __shared__ char smem[];
    const uint32_t sbase = smem_u32(smem);

    float acc[4][8][4];
#pragma unroll
    for (int mi = 0; mi < 4; ++mi)
#pragma unroll
        for (int ni = 0; ni < 8; ++ni)
#pragma unroll
            for (int j = 0; j < 4; ++j) acc[mi][ni][j] = 0.f;

    // ---- staging constants (hoisted once) ----
    const int rS = tid >> 3, cS = tid & 7;                // 16 rows per i-step
    const uint32_t stS = (uint32_t)rS * 128 + (uint32_t)(((cS + ((rS & 1) << 2)) & 7) * 16);
    const __half* pA = A  + (long long)bz * strA + (long long)(m0 + rS) * lda + cS * 8;
    const __half* pB = Bg + (long long)bz * strB + (long long)(n0 + rS) * ldb + cS * 8;
    const long long stepA = (long long)lda * 16;          // 16 rows
    const long long stepB = (long long)ldb * 16;

    auto load_stage = [&](int s) {
        const uint32_t sa = sbase + (uint32_t)s * STAGE_B;
        const uint32_t sb = sa + BM * 128;
#pragma unroll
        for (int i = 0; i < 8; ++i) cp16(sa + stS + i * 2048u, pA + i * stepA);
#pragma unroll
        for (int i = 0; i < 8; ++i) cp16(sb + stS + i * 2048u, pB + i * stepB);
        pA += 64; pB += 64;                               // next k-stage
    };

    const int KT = K / BK;
    load_stage(0); CP_COMMIT();
    if (KT > 1) { load_stage(1); }
    CP_COMMIT();

    const int wm = (wid & 1) * 64, wn = (wid >> 1) * 64;
    const int par = g & 1;
    const uint32_t co0 = (uint32_t)(((tg + 4 * par) & 7) << 4);       // h=0 chunk offset
    const uint32_t co1 = (uint32_t)(((tg + 4 + 4 * par) & 7) << 4);   // h=1 chunk offset
    const uint32_t aRow = (uint32_t)(wm + g) * 128;       // + mi*2048 (+8 rows = +1024)
    const uint32_t bRow = (uint32_t)(wn + g) * 128;       // + ni*1024

    for (int kt = 0; kt < KT; ++kt) {
        CP_WAIT(1);
        __syncthreads();
        const int s = kt % NSTAGE;
        if (kt + 2 < KT) { load_stage((kt + 2) % NSTAGE); }
        CP_COMMIT();

        const char* sa = smem + s * STAGE_B;
        const char* sb = sa + BM * 128;

#pragma unroll
        for (int h = 0; h < 2; ++h) {
            const uint32_t co = h ? co1 : co0;
            // ---- batched fragment loads: 16 LDS.128, no interleaved mma ----
            uint4 vb[8];
#pragma unroll
            for (int ni = 0; ni < 8; ++ni)
                vb[ni] = *reinterpret_cast<const uint4*>(sb + bRow + ni * 1024u + co);
            uint4 va[4][2];
#pragma unroll
            for (int mi = 0; mi < 4; ++mi) {
                va[mi][0] = *reinterpret_cast<const uint4*>(sa + aRow + mi * 2048u + co);
                va[mi][1] = *reinterpret_cast<const uint4*>(sa + aRow + mi * 2048u + 1024u + co);
            }
            // ---- pure HMMA burst: 64 mma, no LDS between ----
#pragma unroll
            for (int mi = 0; mi < 4; ++mi) {
#pragma unroll
                for (int ni = 0; ni < 8; ++ni)
                    mma16(acc[mi][ni], va[mi][0].x, va[mi][1].x, va[mi][0].y, va[mi][1].y,
                          vb[ni].x, vb[ni].y);
#pragma unroll
                for (int ni = 0; ni < 8; ++ni)
                    mma16(acc[mi][ni], va[mi][0].z, va[mi][1].z, va[mi][0].w, va[mi][1].w,
                          vb[ni].z, vb[ni].w);
            }
        }
    }

    // ---- epilogue: direct fragment stores ----
#pragma unroll
    for (int mi = 0; mi < 4; ++mi) {
#pragma unroll
        for (int ni = 0; ni < 8; ++ni) {
            const int row = m0 + wm + 16 * mi + g;
            const int col = n0 + wn + 8 * ni + 2 * tg;
            float v0 = acc[mi][ni][0], v1 = acc[mi][ni][1];
            float v2 = acc[mi][ni][2], v3 = acc[mi][ni][3];
            if (EPI == 1) {
                __half* C = (__half*)Cv + (long long)bz * strC;
                const float2 bv = *reinterpret_cast<const float2*>(&bias[col]);
                *reinterpret_cast<__half2*>(&C[(long long)row * ldc + col]) =
                    __floats2half2_rn(v0 + bv.x, v1 + bv.y);
                *reinterpret_cast<__half2*>(&C[(long long)(row + 8) * ldc + col]) =
                    __floats2half2_rn(v2 + bv.x, v3 + bv.y);
            } else {
                float* C = (float*)Cv + (long long)bz * strC;
                if (EPI == 2) {
                    v0 = (col + 4     <= row)     ? v0 * scale : -65000.f;
                    v1 = (col + 1 + 4 <= row)     ? v1 * scale : -65000.f;
                    v2 = (col + 4     <= row + 8) ? v2 * scale : -65000.f;
                    v3 = (col + 1 + 4 <= row + 8) ? v3 * scale : -65000.f;
                }
                *reinterpret_cast<float2*>(&C[(long long)row * ldc + col])       = make_float2(v0, v1);
                *reinterpret_cast<float2*>(&C[(long long)(row + 8) * ldc + col]) = make_float2(v2, v3);
            }
        }
    }
}

// ---- prep: W -> fp16 merged [Wq;Wk], bias merged fp32 ----
__global__ void prep_w(const float* __restrict__ Wq, const float* __restrict__ Wk,
                       const float* __restrict__ bq, const float* __restrict__ bk,
                       __half* __restrict__ W, float* __restrict__ bias) {
    const int row = blockIdx.x;
    const float* src = (row < NBOT) ? &Wq[(size_t)row * ND] : &Wk[(size_t)(row - NBOT) * ND];
    for (int c = threadIdx.x; c < ND; c += blockDim.x)
        W[(size_t)row * ND + c] = __float2half_rn(src[c]);
    if (threadIdx.x == 0)
        bias[row] = (row < NBOT) ? bq[row] : bk[row - NBOT];
}

// ---- prep: X fp32 -> fp16 copy + fp16 transpose ----
__global__ void transpose_half(const float* __restrict__ X,
                               __half* __restrict__ Xh, __half* __restrict__ Xt) {
    __shared__ float tile[32][33];
    const int b = blockIdx.z;
    const int d0 = blockIdx.x * 32, t0 = blockIdx.y * 32;
    const float* Xb = X  + (long long)b * NT * ND;
    __half* Xhb     = Xh + (long long)b * NT * ND;
    __half* Xtb     = Xt + (long long)b * ND * NT;
    const int tx = threadIdx.x, ty = threadIdx.y;
#pragma unroll
    for (int i = 0; i < 4; ++i) {
        const int t = t0 + ty + i * 8;
        const float v = Xb[(long long)t * ND + d0 + tx];
        Xhb[(long long)t * ND + d0 + tx] = __float2half_rn(v);
        tile[ty + i * 8][tx] = v;
    }
    __syncthreads();
#pragma unroll
    for (int i = 0; i < 4; ++i) {
        const int d = d0 + ty + i * 8;
        Xtb[(long long)d * NT + t0 + tx] = __float2half_rn(tile[tx][ty + i * 8]);
    }
}

// ---- softmax + combine: reads ONLY the allowed prefix (j <= i-4) of S ----
// Masked cols: exp contribution is exactly 0 (matches fp32 reference underflow),
// so C = 0.7*decay there. Rows i<4: fully masked -> uniform softmax 1/NT.
__global__ void __launch_bounds__(256)
softmax_combine(const float* __restrict__ decay, const float* __restrict__ S,
                __half* __restrict__ C)
{
    __shared__ float red[8];
    const int i = blockIdx.x;
    const long long base = ((long long)blockIdx.y * NT + i) * NT;
    const int tid = threadIdx.x;
    const int lane = tid & 31, wid = tid >> 5;
    const int nallow = i - 3;

    if (nallow <= 0) {           // fully masked row: uniform softmax
        const float add = 0.3f / (float)NT;
#pragma unroll
        for (int p = 0; p < 16; ++p) {
            const long long idx = base + tid + 256 * p;
            C[idx] = __float2half_rn(fmaf(0.7f, decay[idx], add));
        }
        return;
    }

    const float NEG = __int_as_float(0xff800000);  // -inf
    float v[16];
#pragma unroll
    for (int p = 0; p < 16; ++p) {
        const int c = tid + 256 * p;
        v[p] = (c < nallow) ? S[base + c] : NEG;
    }

    float mx = v[0];
#pragma unroll
    for (int p = 1; p < 16; ++p) mx = fmaxf(mx, v[p]);
#pragma unroll
    for (int o = 16; o > 0; o >>= 1) mx = fmaxf(mx, __shfl_xor_sync(0xffffffffu, mx, o));
    if (lane == 0) red[wid] = mx;
    __syncthreads();
    float bm = red[0];
#pragma unroll
    for (int i2 = 1; i2 < 8; ++i2) bm = fmaxf(bm, red[i2]);

    float s = 0.f;
#pragma unroll
    for (int p = 0; p < 16; ++p) { v[p] = __expf(v[p] - bm); s += v[p]; }  // masked -> 0
#pragma unroll
    for (int o = 16; o > 0; o >>= 1) s += __shfl_xor_sync(0xffffffffu, s, o);
    __syncthreads();
    if (lane == 0) red[wid] = s;
    __syncthreads();
    float ts = 0.f;
#pragma unroll
    for (int i2 = 0; i2 < 8; ++i2) ts += red[i2];

    const float inv = 0.3f / ts;
#pragma unroll
    for (int p = 0; p < 16; ++p) {
        const long long idx = base + tid + 256 * p;
        C[idx] = __float2half_rn(fmaf(v[p], inv, 0.7f * decay[idx]));  // masked: v=0 -> 0.7d
    }
}

extern "C" void kernel_launch(void* const* d_in, const int* in_sizes, int n_in,
                              void* d_out, int out_size)
{
    (void)in_sizes; (void)n_in; (void)out_size;
    const float* X     = (const float*)d_in[0];
    const float* decay = (const float*)d_in[1];
    const float* Wq    = (const float*)d_in[2];
    const float* bq    = (const float*)d_in[3];
    const float* Wk    = (const float*)d_in[4];
    const float* bk    = (const float*)d_in[5];
    float*       out   = (float*)d_out;

    float  *Sp, *biasp;
    __half *Cp, *Xhp, *Xtp, *qkp, *Wp;
    cudaGetSymbolAddress((void**)&Sp,   g_S);
    cudaGetSymbolAddress((void**)&Cp,   g_C);
    cudaGetSymbolAddress((void**)&Xhp,  g_Xh);
    cudaGetSymbolAddress((void**)&Xtp,  g_Xth);
    cudaGetSymbolAddress((void**)&qkp,  g_qk);
    cudaGetSymbolAddress((void**)&Wp,   g_W);
    cudaGetSymbolAddress((void**)&biasp, g_bias);

    cudaFuncSetAttribute(gemm_h<0>, cudaFuncAttributeMaxDynamicSharedMemorySize, SMEM_BYTES);
    cudaFuncSetAttribute(gemm_h<1>, cudaFuncAttributeMaxDynamicSharedMemorySize, SMEM_BYTES);
    cudaFuncSetAttribute(gemm_h<2>, cudaFuncAttributeMaxDynamicSharedMemorySize, SMEM_BYTES);

    // prep
    prep_w<<<NQK, 256>>>(Wq, Wk, bq, bk, Wp, biasp);
    transpose_half<<<dim3(ND / 32, NT / 32, NB), dim3(32, 8)>>>(X, Xhp, Xtp);

    // qk = X @ [Wq;Wk]^T + bias   (M = B*T = 16384, N = 512, K = 2048) -> fp16
    gemm_h<1><<<dim3(NQK / BN, (NB * NT) / BM, 1), NTH, SMEM_BYTES>>>(
        Xhp, ND, 0LL, Wp, ND, 0LL, qkp, NQK, 0LL, ND, biasp, 1.f);

    // S = scale * q @ k^T (lower-triangular tiles only)  (per batch, M = N = T, K = 256)
    gemm_h<2><<<dim3(NT / BN, NT / BM, NB), NTH, SMEM_BYTES>>>(
        qkp,        NQK, (long long)NT * NQK,
        qkp + NBOT, NQK, (long long)NT * NQK,
        Sp,         NT,  (long long)NT * NT,
        NBOT, nullptr, 0.0625f);

    // combined = 0.7*decay + 0.3*softmax(S)  -> fp16
    softmax_combine<<<dim3(NT, NB), 256>>>(decay, Sp, Cp);

    // out = combined @ X = combined @ Xt^T  (per batch, M = T, N = D, K = T) -> fp32
    gemm_h<0><<<dim3(ND / BN, NT / BM, NB), NTH, SMEM_BYTES>>>(
        Cp,  NT, (long long)NT * NT,
        Xtp, NT, (long long)ND * NT,
        out, ND, (long long)NT * ND,
        NT, nullptr, 1.f);
}

// round 14
// speedup vs baseline: 1.0027x; 1.0027x over previous
#include <cuda_runtime.h>
#include <cuda_fp16.h>
#include <cstdint>

#define NB   4
#define NT   4096
#define ND   2048
#define NBOT 256
#define NQK  512        // merged q|k output width

static constexpr int BM = 128, BN = 128, BK = 64, NTH = 128, NSTAGE = 3;
static constexpr int STAGE_B   = BM * 128 + BN * 128;  // A 16KB + B 16KB (fp16, 128B/row)
static constexpr int SMEM_BYTES = NSTAGE * STAGE_B;    // 96 KB per CTA (2 CTAs/SM = 192 KB)

// ---- scratch (__device__ globals: allocation-free rule) ----
__device__ __align__(256) __half g_Sh[(size_t)NB * NT * NT];    // fp16 scores (lower tri only)
__device__ __align__(256) __half g_C [(size_t)NB * NT * NT];    // fp16 combined matrix
__device__ __align__(256) __half g_Xh [(size_t)NB * NT * ND];   // X  fp16
__device__ __align__(256) __half g_Xth[(size_t)NB * ND * NT];   // X^T fp16
__device__ __align__(256) __half g_qk[(size_t)NB * NT * NQK];   // [q|k] fp16
__device__ __align__(256) __half g_W [(size_t)NQK * ND];        // [Wq;Wk] fp16
__device__ __align__(256) float  g_bias[NQK];

// ---- helpers ----
__device__ __forceinline__ uint32_t smem_u32(const void* p) {
    uint32_t a;
    asm("{ .reg .u64 t; cvta.to.shared.u64 t, %1; cvt.u32.u64 %0, t; }" : "=r"(a) : "l"(p));
    return a;
}
__device__ __forceinline__ void cp16(uint32_t dst, const __half* src) {
    asm volatile("cp.async.cg.shared.global [%0], [%1], 16;\n"
                 :: "r"(dst), "l"(__cvta_generic_to_global(src)));
}
#define CP_COMMIT()  asm volatile("cp.async.commit_group;\n" ::: "memory")
#define CP_WAIT(n)   asm volatile("cp.async.wait_group %0;\n" :: "n"(n) : "memory")

__device__ __forceinline__ void mma16(float* c, uint32_t a0, uint32_t a1, uint32_t a2,
                                      uint32_t a3, uint32_t b0, uint32_t b1) {
    asm volatile(
        "mma.sync.aligned.m16n8k16.row.col.f32.f16.f16.f32 "
        "{%0,%1,%2,%3}, {%4,%5,%6,%7}, {%8,%9}, {%0,%1,%2,%3};\n"
        : "+f"(c[0]), "+f"(c[1]), "+f"(c[2]), "+f"(c[3])
        : "r"(a0), "r"(a1), "r"(a2), "r"(a3), "r"(b0), "r"(b1));
}

// ============================================================================
// fp16 mma.sync GEMM: D[m][n] = sum_k A[m][k] * B[n][k]  (A,B fp16 row-major K-contig)
// EPI: 0 = fp32 store, 1 = +bias -> fp16 store, 2 = scale + causal(-4) mask -> FP16 store
//      (EPI 2: fully-masked tiles (n0 > m0) skipped; softmax reads only the prefix)
// CTA tile 128x128, 4 warps (2m x 2n), warp tile 64x64, BK=64 (128B smem rows),
// 3-stage cp.async ring (2 tiles in flight), __launch_bounds__(128,2) -> 2 CTAs/SM.
// Inner loop: batched fragment LDS then pure HMMA burst (best measured config).
// Smem chunk swizzle: chunk c of row r at c' = (c + 4*(r&1)) & 7 (conflict-free).
// Frag loads use a per-thread k-slot permutation identical for A and B.
// ============================================================================
template <int EPI>
__global__ void __launch_bounds__(NTH, 2)
gemm_h(const __half* __restrict__ A, int lda, long long strA,
       const __half* __restrict__ Bg, int ldb, long long strB,
       void* __restrict__ Cv, int ldc, long long strC,
       int K, const float* __restrict__ bias, float scale)
{
    const int m0 = blockIdx.y * BM;
    const int n0 = blockIdx.x * BN;
    const int bz = blockIdx.z;
    if (EPI == 2 && n0 > m0) return;   // fully masked tile: never written, never read

    const int tid = threadIdx.x, wid = tid >> 5, lane = tid & 31;
    const int g = lane >> 2, tg = lane & 3;

    extern __shared__ char smem[];
    const uint32_t sbase = smem_u32(smem);

    float acc[4][8][4];
#pragma unroll
    for (int mi = 0; mi < 4; ++mi)
#pragma unroll
        for (int ni = 0; ni < 8; ++ni)
#pragma unroll
            for (int j = 0; j < 4; ++j) acc[mi][ni][j] = 0.f;

    // ---- staging constants (hoisted once) ----
    const int rS = tid >> 3, cS = tid & 7;                // 16 rows per i-step
    const uint32_t stS = (uint32_t)rS * 128 + (uint32_t)(((cS + ((rS & 1) << 2)) & 7) * 16);
    const __half* pA = A  + (long long)bz * strA + (long long)(m0 + rS) * lda + cS * 8;
    const __half* pB = Bg + (long long)bz * strB + (long long)(n0 + rS) * ldb + cS * 8;
    const long long stepA = (long long)lda * 16;          // 16 rows
    const long long stepB = (long long)ldb * 16;

    auto load_stage = [&](int s) {
        const uint32_t sa = sbase + (uint32_t)s * STAGE_B;
        const uint32_t sb = sa + BM * 128;
#pragma unroll
        for (int i = 0; i < 8; ++i) cp16(sa + stS + i * 2048u, pA + i * stepA);
#pragma unroll
        for (int i = 0; i < 8; ++i) cp16(sb + stS + i * 2048u, pB + i * stepB);
        pA += 64; pB += 64;                               // next k-stage
    };

    const int KT = K / BK;
    load_stage(0); CP_COMMIT();
    if (KT > 1) { load_stage(1); }
    CP_COMMIT();

    const int wm = (wid & 1) * 64, wn = (wid >> 1) * 64;
    const int par = g & 1;
    const uint32_t co0 = (uint32_t)(((tg + 4 * par) & 7) << 4);       // h=0 chunk offset
    const uint32_t co1 = (uint32_t)(((tg + 4 + 4 * par) & 7) << 4);   // h=1 chunk offset
    const uint32_t aRow = (uint32_t)(wm + g) * 128;       // + mi*2048 (+8 rows = +1024)
    const uint32_t bRow = (uint32_t)(wn + g) * 128;       // + ni*1024

    for (int kt = 0; kt < KT; ++kt) {
        CP_WAIT(1);
        __syncthreads();
        const int s = kt % NSTAGE;
        if (kt + 2 < KT) { load_stage((kt + 2) % NSTAGE); }
        CP_COMMIT();

        const char* sa = smem + s * STAGE_B;
        const char* sb = sa + BM * 128;

#pragma unroll
        for (int h = 0; h < 2; ++h) {
            const uint32_t co = h ? co1 : co0;
            uint4 vb[8];
#pragma unroll
            for (int ni = 0; ni < 8; ++ni)
                vb[ni] = *reinterpret_cast<const uint4*>(sb + bRow + ni * 1024u + co);
            uint4 va[4][2];
#pragma unroll
            for (int mi = 0; mi < 4; ++mi) {
                va[mi][0] = *reinterpret_cast<const uint4*>(sa + aRow + mi * 2048u + co);
                va[mi][1] = *reinterpret_cast<const uint4*>(sa + aRow + mi * 2048u + 1024u + co);
            }
#pragma unroll
            for (int mi = 0; mi < 4; ++mi) {
#pragma unroll
                for (int ni = 0; ni < 8; ++ni)
                    mma16(acc[mi][ni], va[mi][0].x, va[mi][1].x, va[mi][0].y, va[mi][1].y,
                          vb[ni].x, vb[ni].y);
#pragma unroll
                for (int ni = 0; ni < 8; ++ni)
                    mma16(acc[mi][ni], va[mi][0].z, va[mi][1].z, va[mi][0].w, va[mi][1].w,
                          vb[ni].z, vb[ni].w);
            }
        }
    }

    // ---- epilogue: direct fragment stores ----
#pragma unroll
    for (int mi = 0; mi < 4; ++mi) {
#pragma unroll
        for (int ni = 0; ni < 8; ++ni) {
            const int row = m0 + wm + 16 * mi + g;
            const int col = n0 + wn + 8 * ni + 2 * tg;
            float v0 = acc[mi][ni][0], v1 = acc[mi][ni][1];
            float v2 = acc[mi][ni][2], v3 = acc[mi][ni][3];
            if (EPI == 1) {
                __half* C = (__half*)Cv + (long long)bz * strC;
                const float2 bv = *reinterpret_cast<const float2*>(&bias[col]);
                *reinterpret_cast<__half2*>(&C[(long long)row * ldc + col]) =
                    __floats2half2_rn(v0 + bv.x, v1 + bv.y);
                *reinterpret_cast<__half2*>(&C[(long long)(row + 8) * ldc + col]) =
                    __floats2half2_rn(v2 + bv.x, v3 + bv.y);
            } else if (EPI == 2) {
                __half* C = (__half*)Cv + (long long)bz * strC;
                v0 = (col + 4     <= row)     ? v0 * scale : -65000.f;
                v1 = (col + 1 + 4 <= row)     ? v1 * scale : -65000.f;
                v2 = (col + 4     <= row + 8) ? v2 * scale : -65000.f;
                v3 = (col + 1 + 4 <= row + 8) ? v3 * scale : -65000.f;
                *reinterpret_cast<__half2*>(&C[(long long)row * ldc + col]) =
                    __floats2half2_rn(v0, v1);
                *reinterpret_cast<__half2*>(&C[(long long)(row + 8) * ldc + col]) =
                    __floats2half2_rn(v2, v3);
            } else {
                float* C = (float*)Cv + (long long)bz * strC;
                *reinterpret_cast<float2*>(&C[(long long)row * ldc + col])       = make_float2(v0, v1);
                *reinterpret_cast<float2*>(&C[(long long)(row + 8) * ldc + col]) = make_float2(v2, v3);
            }
        }
    }
}

// ---- prep: W -> fp16 merged [Wq;Wk], bias merged fp32 ----
__global__ void prep_w(const float* __restrict__ Wq, const float* __restrict__ Wk,
                       const float* __restrict__ bq, const float* __restrict__ bk,
                       __half* __restrict__ W, float* __restrict__ bias) {
    const int row = blockIdx.x;
    const float* src = (row < NBOT) ? &Wq[(size_t)row * ND] : &Wk[(size_t)(row - NBOT) * ND];
    for (int c = threadIdx.x; c < ND; c += blockDim.x)
        W[(size_t)row * ND + c] = __float2half_rn(src[c]);
    if (threadIdx.x == 0)
        bias[row] = (row < NBOT) ? bq[row] : bk[row - NBOT];
}

// ---- prep: X fp32 -> fp16 copy + fp16 transpose ----
__global__ void transpose_half(const float* __restrict__ X,
                               __half* __restrict__ Xh, __half* __restrict__ Xt) {
    __shared__ float tile[32][33];
    const int b = blockIdx.z;
    const int d0 = blockIdx.x * 32, t0 = blockIdx.y * 32;
    const float* Xb = X  + (long long)b * NT * ND;
    __half* Xhb     = Xh + (long long)b * NT * ND;
    __half* Xtb     = Xt + (long long)b * ND * NT;
    const int tx = threadIdx.x, ty = threadIdx.y;
#pragma unroll
    for (int i = 0; i < 4; ++i) {
        const int t = t0 + ty + i * 8;
        const float v = Xb[(long long)t * ND + d0 + tx];
        Xhb[(long long)t * ND + d0 + tx] = __float2half_rn(v);
        tile[ty + i * 8][tx] = v;
    }
    __syncthreads();
#pragma unroll
    for (int i = 0; i < 4; ++i) {
        const int d = d0 + ty + i * 8;
        Xtb[(long long)d * NT + t0 + tx] = __float2half_rn(tile[tx][ty + i * 8]);
    }
}

// ---- softmax + combine: reads ONLY the allowed prefix (j <= i-4) of fp16 S ----
// Masked cols: exp contribution is exactly 0 (matches fp32 reference underflow),
// so C = 0.7*decay there. Rows i<4: fully masked -> uniform softmax 1/NT.
__global__ void __launch_bounds__(256)
softmax_combine(const float* __restrict__ decay, const __half* __restrict__ S,
                __half* __restrict__ C)
{
    __shared__ float red[8];
    const int i = blockIdx.x;
    const long long base = ((long long)blockIdx.y * NT + i) * NT;
    const int tid = threadIdx.x;
    const int lane = tid & 31, wid = tid >> 5;
    const int nallow = i - 3;

    if (nallow <= 0) {           // fully masked row: uniform softmax
        const float add = 0.3f / (float)NT;
#pragma unroll
        for (int p = 0; p < 16; ++p) {
            const long long idx = base + tid + 256 * p;
            C[idx] = __float2half_rn(fmaf(0.7f, decay[idx], add));
        }
        return;
    }

    const float NEG = __int_as_float(0xff800000);  // -inf
    float v[16];
#pragma unroll
    for (int p = 0; p < 16; ++p) {
        const int c = tid + 256 * p;
        v[p] = (c < nallow) ? __half2float(S[base + c]) : NEG;
    }

    float mx = v[0];
#pragma unroll
    for (int p = 1; p < 16; ++p) mx = fmaxf(mx, v[p]);
#pragma unroll
    for (int o = 16; o > 0; o >>= 1) mx = fmaxf(mx, __shfl_xor_sync(0xffffffffu, mx, o));
    if (lane == 0) red[wid] = mx;
    __syncthreads();
    float bm = red[0];
#pragma unroll
    for (int i2 = 1; i2 < 8; ++i2) bm = fmaxf(bm, red[i2]);

    float s = 0.f;
#pragma unroll
    for (int p = 0; p < 16; ++p) { v[p] = __expf(v[p] - bm); s += v[p]; }  // masked -> 0
#pragma unroll
    for (int o = 16; o > 0; o >>= 1) s += __shfl_xor_sync(0xffffffffu, s, o);
    __syncthreads();
    if (lane == 0) red[wid] = s;
    __syncthreads();
    float ts = 0.f;
#pragma unroll
    for (int i2 = 0; i2 < 8; ++i2) ts += red[i2];

    const float inv = 0.3f / ts;
#pragma unroll
    for (int p = 0; p < 16; ++p) {
        const long long idx = base + tid + 256 * p;
        C[idx] = __float2half_rn(fmaf(v[p], inv, 0.7f * decay[idx]));  // masked: v=0 -> 0.7d
    }
}

extern "C" void kernel_launch(void* const* d_in, const int* in_sizes, int n_in,
                              void* d_out, int out_size)
{
    (void)in_sizes; (void)n_in; (void)out_size;
    const float* X     = (const float*)d_in[0];
    const float* decay = (const float*)d_in[1];
    const float* Wq    = (const float*)d_in[2];
    const float* bq    = (const float*)d_in[3];
    const float* Wk    = (const float*)d_in[4];
    const float* bk    = (const float*)d_in[5];
    float*       out   = (float*)d_out;

    float  *biasp;
    __half *Shp, *Cp, *Xhp, *Xtp, *qkp, *Wp;
    cudaGetSymbolAddress((void**)&Shp,  g_Sh);
    cudaGetSymbolAddress((void**)&Cp,   g_C);
    cudaGetSymbolAddress((void**)&Xhp,  g_Xh);
    cudaGetSymbolAddress((void**)&Xtp,  g_Xth);
    cudaGetSymbolAddress((void**)&qkp,  g_qk);
    cudaGetSymbolAddress((void**)&Wp,   g_W);
    cudaGetSymbolAddress((void**)&biasp, g_bias);

    cudaFuncSetAttribute(gemm_h<0>, cudaFuncAttributeMaxDynamicSharedMemorySize, SMEM_BYTES);
    cudaFuncSetAttribute(gemm_h<1>, cudaFuncAttributeMaxDynamicSharedMemorySize, SMEM_BYTES);
    cudaFuncSetAttribute(gemm_h<2>, cudaFuncAttributeMaxDynamicSharedMemorySize, SMEM_BYTES);

    // prep
    prep_w<<<NQK, 256>>>(Wq, Wk, bq, bk, Wp, biasp);
    transpose_half<<<dim3(ND / 32, NT / 32, NB), dim3(32, 8)>>>(X, Xhp, Xtp);

    // qk = X @ [Wq;Wk]^T + bias   (M = B*T = 16384, N = 512, K = 2048) -> fp16
    gemm_h<1><<<dim3(NQK / BN, (NB * NT) / BM, 1), NTH, SMEM_BYTES>>>(
        Xhp, ND, 0LL, Wp, ND, 0LL, qkp, NQK, 0LL, ND, biasp, 1.f);

    // S = scale * q @ k^T (lower-triangular tiles only) -> fp16  (per batch, K = 256)
    gemm_h<2><<<dim3(NT / BN, NT / BM, NB), NTH, SMEM_BYTES>>>(
        qkp,        NQK, (long long)NT * NQK,
        qkp + NBOT, NQK, (long long)NT * NQK,
        Shp,        NT,  (long long)NT * NT,
        NBOT, nullptr, 0.0625f);

    // combined = 0.7*decay + 0.3*softmax(S)  -> fp16
    softmax_combine<<<dim3(NT, NB), 256>>>(decay, Shp, Cp);

    // out = combined @ X = combined @ Xt^T  (per batch, M = T, N = D, K = T) -> fp32
    gemm_h<0><<<dim3(ND / BN, NT / BM, NB), NTH, SMEM_BYTES>>>(
        Cp,  NT, (long long)NT * NT,
        Xtp, NT, (long long)ND * NT,
        out, ND, (long long)NT * ND,
        NT, nullptr, 1.f);
}